// round 2
// baseline (speedup 1.0000x reference)
#include <cuda_runtime.h>
#include <math.h>

// Problem constants (fixed shapes for this problem instance)
#define HID   1024
#define BSZ   16
#define NOPT  4
#define ROWS  (BSZ*NOPT)    // 64
#define TRUN  2
#define SEQ   1536
#define PLEN  512
#define QLEN  128

// Scratch (device globals — no allocation allowed)
__device__ float g_feats[ROWS*HID];
__device__ float g_h1[ROWS*HID];
__device__ float g_h2[ROWS*HID];
__device__ float g_logits[ROWS];

// ---------------------------------------------------------------------------
// 1) Init accumulators with biases (split-K GEMMs accumulate on top via atomics)
// ---------------------------------------------------------------------------
__global__ void init_kernel(const float* __restrict__ b1, const float* __restrict__ b2) {
    int i = blockIdx.x * blockDim.x + threadIdx.x;   // 0..65535
    int j = i & (HID - 1);
    g_h1[i] = b1[j];
    g_h2[i] = b2[j];
}

// ---------------------------------------------------------------------------
// 2) feats[b*4+o][h] = 0.25 * sum over (trun, 6 positions) of embeddings
//    opt_length dtype-robust: harness may store it as int32 or int64.
// ---------------------------------------------------------------------------
__device__ __forceinline__ long long opt_at(const void* p, bool is64, int i) {
    if (is64) return ((const long long*)p)[i];
    return (long long)((const int*)p)[i];
}

__global__ void feats_kernel(const float* __restrict__ emb,
                             const void* __restrict__ opt_length) {
    int row = blockIdx.x;            // b*NOPT + o
    int b = row >> 2, o = row & 3;

    // int64 array [0,128,128,128,128] viewed as int32 gives [0,0,128,0,...]
    // -> element 1 == 0 identifies int64 storage; int32 storage has 128 there.
    bool is64 = (((const int*)opt_length)[1] == 0);

    long long cs = 0;
    for (int i = 0; i <= o; i++) cs += opt_at(opt_length, is64, i);  // cumsum(opt)[o]
    int ohead = PLEN + QLEN + (int)cs;
    int otail = ohead + (int)opt_at(opt_length, is64, o + 1) - 1;

    int pos[6] = {0, PLEN - 1, PLEN, PLEN + QLEN - 1, ohead, otail};

    int h4 = threadIdx.x * 4;        // 256 threads * float4 = 1024
    float4 acc = make_float4(0.f, 0.f, 0.f, 0.f);
    #pragma unroll
    for (int t = 0; t < TRUN; t++) {
        const float* base = emb + (size_t)(t * BSZ + b) * SEQ * HID;
        #pragma unroll
        for (int p = 0; p < 6; p++) {
            float4 v = *(const float4*)(base + (size_t)pos[p] * HID + h4);
            acc.x += v.x; acc.y += v.y; acc.z += v.z; acc.w += v.w;
        }
    }
    const float s = 0.25f;
    float4 out = make_float4(acc.x * s, acc.y * s, acc.z * s, acc.w * s);
    *(float4*)(g_feats + (size_t)row * HID + h4) = out;
}

// ---------------------------------------------------------------------------
// 3) Split-K GEMM: out += A(64xK) @ W(KxN), 64x64x64 tiles.
//    LAYER 0: A = g_feats (no relu), out = g_h1 (pre-init b1)
//    LAYER 1: A = relu(g_h1),        out = g_h2 (pre-init b2)
//    Grid: (N/64=16, K/64=16) = 256 blocks, 256 threads, 4x4 microtiles.
// ---------------------------------------------------------------------------
template <int LAYER>
__global__ void __launch_bounds__(256, 4)
gemm_kernel(const float* __restrict__ W) {
    __shared__ float As[64][65];   // [row][k], pad to kill write conflicts
    __shared__ float Ws[64][64];   // [k][col]

    const float* A  = (LAYER == 0) ? g_feats : g_h1;
    float*      out = (LAYER == 0) ? g_h1    : g_h2;

    int n0 = blockIdx.x * 64;
    int k0 = blockIdx.y * 64;
    int tid = threadIdx.x;

    // Load A tile (coalesced over k)
    #pragma unroll
    for (int idx = tid; idx < 64 * 64; idx += 256) {
        int r = idx >> 6, kk = idx & 63;
        float v = A[(size_t)r * HID + k0 + kk];
        if (LAYER == 1) v = fmaxf(v, 0.f);
        As[r][kk] = v;
    }
    // Load W tile (coalesced over n)
    #pragma unroll
    for (int idx = tid; idx < 64 * 64; idx += 256) {
        int kk = idx >> 6, c = idx & 63;
        Ws[kk][c] = W[(size_t)(k0 + kk) * HID + n0 + c];
    }
    __syncthreads();

    int c0 = (tid & 15) * 4;
    int r0 = (tid >> 4) * 4;

    float acc[4][4] = {};
    #pragma unroll 8
    for (int kk = 0; kk < 64; kk++) {
        float4 w = *(const float4*)&Ws[kk][c0];
        float a0 = As[r0 + 0][kk];
        float a1 = As[r0 + 1][kk];
        float a2 = As[r0 + 2][kk];
        float a3 = As[r0 + 3][kk];
        acc[0][0] += a0 * w.x; acc[0][1] += a0 * w.y; acc[0][2] += a0 * w.z; acc[0][3] += a0 * w.w;
        acc[1][0] += a1 * w.x; acc[1][1] += a1 * w.y; acc[1][2] += a1 * w.z; acc[1][3] += a1 * w.w;
        acc[2][0] += a2 * w.x; acc[2][1] += a2 * w.y; acc[2][2] += a2 * w.z; acc[2][3] += a2 * w.w;
        acc[3][0] += a3 * w.x; acc[3][1] += a3 * w.y; acc[3][2] += a3 * w.z; acc[3][3] += a3 * w.w;
    }

    #pragma unroll
    for (int i = 0; i < 4; i++)
        #pragma unroll
        for (int j = 0; j < 4; j++)
            atomicAdd(&out[(size_t)(r0 + i) * HID + n0 + c0 + j], acc[i][j]);
}

// ---------------------------------------------------------------------------
// 4) logits[row] = relu(g_h2[row]) . W3
// ---------------------------------------------------------------------------
__global__ void gemv_kernel(const float* __restrict__ W3) {
    int row = blockIdx.x;
    const float* h = g_h2 + (size_t)row * HID;
    float s = 0.f;
    #pragma unroll
    for (int k = threadIdx.x; k < HID; k += 128)
        s += fmaxf(h[k], 0.f) * W3[k];

    #pragma unroll
    for (int off = 16; off; off >>= 1)
        s += __shfl_down_sync(0xFFFFFFFFu, s, off);

    __shared__ float red[4];
    if ((threadIdx.x & 31) == 0) red[threadIdx.x >> 5] = s;
    __syncthreads();
    if (threadIdx.x == 0)
        g_logits[row] = red[0] + red[1] + red[2] + red[3];
}

// ---------------------------------------------------------------------------
// 5) result + log_softmax loss
// ---------------------------------------------------------------------------
__global__ void loss_kernel(const int* __restrict__ y, float* __restrict__ out,
                            int out_size) {
    int tid = threadIdx.x;   // 32 threads
    float l[NOPT];
    float loss_part = 0.f;
    if (tid < BSZ) {
        float m = -1e30f;
        #pragma unroll
        for (int o = 0; o < NOPT; o++) {
            l[o] = g_logits[tid * NOPT + o];
            m = fmaxf(m, l[o]);
        }
        float se = 0.f;
        #pragma unroll
        for (int o = 0; o < NOPT; o++) se += expf(l[o] - m);
        float lse = m + logf(se);
        int yy = y[tid];
        loss_part = -(l[yy] - lse);

        if (out_size >= ROWS) {
            #pragma unroll
            for (int o = 0; o < NOPT; o++) out[tid * NOPT + o] = l[o];
        }
    }
    #pragma unroll
    for (int off = 16; off; off >>= 1)
        loss_part += __shfl_down_sync(0xFFFFFFFFu, loss_part, off);

    if (tid == 0) {
        float loss = loss_part / (float)BSZ;
        if (out_size == 1)             out[0] = loss;
        else if (out_size >= ROWS + 1) out[ROWS] = loss;
    }
}

// ---------------------------------------------------------------------------
// Launch
// inputs: 0=embeddings 1=W1 2=b1 3=W2 4=b2 5=W3 6=y 7=opt_length (then scalars)
// ---------------------------------------------------------------------------
extern "C" void kernel_launch(void* const* d_in, const int* in_sizes, int n_in,
                              void* d_out, int out_size) {
    const float* emb = (const float*)d_in[0];
    const float* W1  = (const float*)d_in[1];
    const float* b1  = (const float*)d_in[2];
    const float* W2  = (const float*)d_in[3];
    const float* b2  = (const float*)d_in[4];
    const float* W3  = (const float*)d_in[5];
    const int*   y   = (const int*)d_in[6];
    const void*  opt = (const void*)d_in[7];
    float* out = (float*)d_out;

    init_kernel<<<256, 256>>>(b1, b2);
    feats_kernel<<<ROWS, 256>>>(emb, opt);
    gemm_kernel<0><<<dim3(16, 16), 256>>>(W1);
    gemm_kernel<1><<<dim3(16, 16), 256>>>(W2);
    gemv_kernel<<<ROWS, 128>>>(W3);
    loss_kernel<<<1, 32>>>(y, out, out_size);
}